// round 13
// baseline (speedup 1.0000x reference)
#include <cuda_runtime.h>
#include <cuda_bf16.h>
#include <math.h>
#include <stdint.h>

#define NN 4096
#define DD 256

// ---------------- scratch (device globals; no allocation allowed) ----------------
__device__ float g_spa_emb[NN * DD];
__device__ float g_tmp_emb[NN * DD];
__device__ float g_node_fea[NN * DD];
__device__ float g_spa_fea[NN * DD];
__device__ float g_tmp_fea[NN * DD];
__device__ float g_val[NN * DD];
__device__ float g_master_s[NN * DD];
__device__ float g_master_t[NN * DD];
__device__ float g_deg_s[NN];
__device__ float g_deg_t[NN];
__device__ float g_rowabs_s[NN];
__device__ float g_rowsq_s[NN];
__device__ float g_rowabs_t[NN];
__device__ float g_rowsq_t[NN];
__device__ float g_sqpart_s[64];
__device__ float g_sqpart_t[64];
// pre-split, pre-transposed X: [D][N] bf16 hi/lo
__device__ __nv_bfloat16 g_bhi_s[DD * NN];
__device__ __nv_bfloat16 g_blo_s[DD * NN];
__device__ __nv_bfloat16 g_bhi_t[DD * NN];
__device__ __nv_bfloat16 g_blo_t[DD * NN];
// pre-split incidence matrices (scattered, zero-diag for spatial), [N][N] bf16
__device__ __nv_bfloat16 g_am_s[(size_t)NN * NN];   // raw
__device__ __nv_bfloat16 g_rh_s[(size_t)NN * NN];   // relu hi
__device__ __nv_bfloat16 g_rl_s[(size_t)NN * NN];   // relu lo
__device__ __nv_bfloat16 g_am_t[(size_t)NN * NN];
__device__ __nv_bfloat16 g_rh_t[(size_t)NN * NN];
__device__ __nv_bfloat16 g_rl_t[(size_t)NN * NN];
// pre-split weights, K-major [n][k]: 0:rpsT 1:rptT 2:nodeT 3:spaT 4:tmpT 5:theta direct
__device__ __nv_bfloat16 g_whi[6 * DD * DD];
__device__ __nv_bfloat16 g_wlo[6 * DD * DD];

// ---------------- PTX helpers (sm_80-baseline only) ----------------
__device__ __forceinline__ uint32_t smem_to_u32(const void* p) {
    uint32_t a;
    asm("{ .reg .u64 t; cvta.to.shared.u64 t, %1; cvt.u32.u64 %0, t; }" : "=r"(a) : "l"(p));
    return a;
}

__device__ __forceinline__ void ldsm4(uint32_t& r0, uint32_t& r1, uint32_t& r2, uint32_t& r3,
                                      uint32_t addr) {
    asm volatile("ldmatrix.sync.aligned.m8n8.x4.shared.b16 {%0,%1,%2,%3}, [%4];"
                 : "=r"(r0), "=r"(r1), "=r"(r2), "=r"(r3) : "r"(addr));
}

__device__ __forceinline__ void mma16816(float* c, const uint32_t* a, const uint32_t* b) {
    asm volatile("mma.sync.aligned.m16n8k16.row.col.f32.bf16.bf16.f32 "
                 "{%0,%1,%2,%3}, {%4,%5,%6,%7}, {%8,%9}, {%0,%1,%2,%3};"
                 : "+f"(c[0]), "+f"(c[1]), "+f"(c[2]), "+f"(c[3])
                 : "r"(a[0]), "r"(a[1]), "r"(a[2]), "r"(a[3]), "r"(b[0]), "r"(b[1]));
}

__device__ __forceinline__ void cpa16(uint32_t dst, const void* src) {
    asm volatile("cp.async.cg.shared.global [%0], [%1], 16;" :: "r"(dst), "l"(src));
}
#define CP_COMMIT() asm volatile("cp.async.commit_group;" ::: "memory")
#define CP_WAIT0()  asm volatile("cp.async.wait_group 0;" ::: "memory")
#define CP_WAIT2()  asm volatile("cp.async.wait_group 2;" ::: "memory")

// ---------------- helpers ----------------
__device__ __forceinline__ float block_sum_256(float v, float* red) {
    int t = threadIdx.x;
    red[t] = v;
    __syncthreads();
#pragma unroll
    for (int s = 128; s > 0; s >>= 1) {
        if (t < s) red[t] += red[t + s];
        __syncthreads();
    }
    float r = red[0];
    __syncthreads();
    return r;
}

__device__ __forceinline__ float block_sum_512(float v, float* red) {
    int t = threadIdx.x;
    red[t] = v;
    __syncthreads();
#pragma unroll
    for (int s = 256; s > 0; s >>= 1) {
        if (t < s) red[t] += red[t + s];
        __syncthreads();
    }
    float r = red[0];
    __syncthreads();
    return r;
}

// ---------------- K0a: incidence pre-split (+ fused row reductions) ----------------
__global__ __launch_bounds__(256) void presplit_kernel(
    const float* __restrict__ inc_s, const float* __restrict__ inc_t,
    __nv_bfloat16* __restrict__ am_s, __nv_bfloat16* __restrict__ rh_s,
    __nv_bfloat16* __restrict__ rl_s,
    __nv_bfloat16* __restrict__ am_t, __nv_bfloat16* __restrict__ rh_t,
    __nv_bfloat16* __restrict__ rl_t,
    float* __restrict__ rowabs_s, float* __restrict__ rowsq_s, float* __restrict__ deg_s,
    float* __restrict__ rowabs_t, float* __restrict__ rowsq_t, float* __restrict__ deg_t)
{
    __shared__ float red[256];
    const int i = blockIdx.x;
    const bool sp = (blockIdx.y == 0);
    const float* inc = sp ? inc_s : inc_t;
    __nv_bfloat16* am = sp ? am_s : am_t;
    __nv_bfloat16* rh = sp ? rh_s : rh_t;
    __nv_bfloat16* rl = sp ? rl_s : rl_t;
    const int t = threadIdx.x;
    const int j0 = t * 16;

    float v[16];
    if (sp) {
        const float* rp = inc + (size_t)i * (NN - 1);
#pragma unroll
        for (int c = 0; c < 16; c++) {
            int j = j0 + c;
            v[c] = (j == i) ? 0.f : __ldg(&rp[j < i ? j : j - 1]);
        }
    } else {
        const float* rp = inc + (size_t)i * NN + j0;
#pragma unroll
        for (int c = 0; c < 16; c += 4) {
            float4 q = *(const float4*)&rp[c];
            v[c] = q.x; v[c + 1] = q.y; v[c + 2] = q.z; v[c + 3] = q.w;
        }
    }

    float sa = 0.f, ss = 0.f, sd = 0.f;
    uint4 um[2], uh[2], ul[2];
#pragma unroll
    for (int c = 0; c < 16; c += 2) {
        float v0 = v[c], v1 = v[c + 1];
        sa += fabsf(v0) + fabsf(v1);
        ss = fmaf(v0, v0, fmaf(v1, v1, ss));
        float r0 = fmaxf(v0, 0.f), r1 = fmaxf(v1, 0.f);
        sd += r0 + r1;
        __nv_bfloat16 h0 = __float2bfloat16(r0), h1 = __float2bfloat16(r1);
        __nv_bfloat16 l0 = __float2bfloat16(r0 - __bfloat162float(h0));
        __nv_bfloat16 l1 = __float2bfloat16(r1 - __bfloat162float(h1));
        __nv_bfloat162 mp = __halves2bfloat162(__float2bfloat16(v0), __float2bfloat16(v1));
        __nv_bfloat162 hp = __halves2bfloat162(h0, h1);
        __nv_bfloat162 lp = __halves2bfloat162(l0, l1);
        ((uint32_t*)um)[c >> 1] = *(uint32_t*)&mp;
        ((uint32_t*)uh)[c >> 1] = *(uint32_t*)&hp;
        ((uint32_t*)ul)[c >> 1] = *(uint32_t*)&lp;
    }
    size_t o = (size_t)i * NN + j0;
    *(uint4*)&am[o] = um[0]; *(uint4*)&am[o + 8] = um[1];
    *(uint4*)&rh[o] = uh[0]; *(uint4*)&rh[o + 8] = uh[1];
    *(uint4*)&rl[o] = ul[0]; *(uint4*)&rl[o + 8] = ul[1];

    sa = block_sum_256(sa, red);
    ss = block_sum_256(ss, red);
    sd = block_sum_256(sd, red);
    if (t == 0) {
        if (sp) { rowabs_s[i] = sa; rowsq_s[i] = ss; deg_s[i] = sd + 1.0f; }
        else    { rowabs_t[i] = sa; rowsq_t[i] = ss; deg_t[i] = sd + 1.0f; }
    }
}

// ---------------- K0b: transpose + bf16 split of X: [N,D] fp32 -> [D,N] hi/lo ----------------
__global__ __launch_bounds__(256) void bsplit_kernel(
    const float* __restrict__ cur, const float* __restrict__ pre,
    __nv_bfloat16* __restrict__ hs, __nv_bfloat16* __restrict__ ls,
    __nv_bfloat16* __restrict__ ht, __nv_bfloat16* __restrict__ lt)
{
    __shared__ float tile[64][68];
    const int z = blockIdx.z;
    const float* X = z ? pre : cur;
    __nv_bfloat16* hi = z ? ht : hs;
    __nv_bfloat16* lo = z ? lt : ls;
    const int j0 = blockIdx.x * 64;
    const int d0 = blockIdx.y * 64;
    const int tid = threadIdx.x;
#pragma unroll
    for (int t = 0; t < 4; t++) {
        int idx = tid + 256 * t;
        int jj = idx >> 4, c4 = (idx & 15) * 4;
        float4 v = *(const float4*)&X[(size_t)(j0 + jj) * DD + d0 + c4];
        tile[jj][c4 + 0] = v.x; tile[jj][c4 + 1] = v.y;
        tile[jj][c4 + 2] = v.z; tile[jj][c4 + 3] = v.w;
    }
    __syncthreads();
#pragma unroll
    for (int t = 0; t < 4; t++) {
        int idx = tid + 256 * t;
        int dd = idx >> 4, q = (idx & 15) * 4;
        __nv_bfloat16 h[4], l[4];
#pragma unroll
        for (int k = 0; k < 4; k++) {
            float v = tile[q + k][dd];
            h[k] = __float2bfloat16(v);
            l[k] = __float2bfloat16(v - __bfloat162float(h[k]));
        }
        size_t o = (size_t)(d0 + dd) * NN + j0 + q;
        *(__nv_bfloat162*)&hi[o]     = __halves2bfloat162(h[0], h[1]);
        *(__nv_bfloat162*)&hi[o + 2] = __halves2bfloat162(h[2], h[3]);
        *(__nv_bfloat162*)&lo[o]     = __halves2bfloat162(l[0], l[1]);
        *(__nv_bfloat162*)&lo[o + 2] = __halves2bfloat162(l[2], l[3]);
    }
}

// ---------------- K0c: weight transpose + split ----------------
__global__ __launch_bounds__(256) void wsplit_kernel(
    const float* __restrict__ rps, const float* __restrict__ rpt,
    const float* __restrict__ np, const float* __restrict__ sp,
    const float* __restrict__ tp, const float* __restrict__ th,
    __nv_bfloat16* __restrict__ whi, __nv_bfloat16* __restrict__ wlo)
{
    __shared__ float tile[64][65];
    const int z = blockIdx.z;
    const float* W = (z == 0) ? rps : (z == 1) ? rpt : (z == 2) ? np
                    : (z == 3) ? sp : (z == 4) ? tp : th;
    const bool tr = (z < 5);
    const int r0 = blockIdx.y * 64, c0 = blockIdx.x * 64;
    const int tid = threadIdx.x;
#pragma unroll
    for (int t = 0; t < 4; t++) {
        int q = tid + 256 * t;
        int rr = q >> 4, c4 = (q & 15) * 4;
        float4 v = *(const float4*)&W[(size_t)(r0 + rr) * DD + c0 + c4];
        tile[rr][c4 + 0] = v.x; tile[rr][c4 + 1] = v.y;
        tile[rr][c4 + 2] = v.z; tile[rr][c4 + 3] = v.w;
    }
    __syncthreads();
    __nv_bfloat16* hi = whi + (size_t)z * DD * DD;
    __nv_bfloat16* lo = wlo + (size_t)z * DD * DD;
#pragma unroll
    for (int t = 0; t < 4; t++) {
        int q = tid + 256 * t;
        int rr = q >> 4, c4 = (q & 15) * 4;
        float v[4];
        size_t o;
        if (tr) {
#pragma unroll
            for (int j = 0; j < 4; j++) v[j] = tile[c4 + j][rr];
            o = (size_t)(c0 + rr) * DD + r0 + c4;
        } else {
#pragma unroll
            for (int j = 0; j < 4; j++) v[j] = tile[rr][c4 + j];
            o = (size_t)(r0 + rr) * DD + c0 + c4;
        }
        __nv_bfloat16 h[4], l[4];
#pragma unroll
        for (int j = 0; j < 4; j++) {
            h[j] = __float2bfloat16(v[j]);
            l[j] = __float2bfloat16(v[j] - __bfloat162float(h[j]));
        }
        *(__nv_bfloat162*)&hi[o]     = __halves2bfloat162(h[0], h[1]);
        *(__nv_bfloat162*)&hi[o + 2] = __halves2bfloat162(h[2], h[3]);
        *(__nv_bfloat162*)&lo[o]     = __halves2bfloat162(l[0], l[1]);
        *(__nv_bfloat162*)&lo[o + 2] = __halves2bfloat162(l[2], l[3]);
    }
}

// ---------------- BIG: mma.sync bf16 fused incidence GEMM — 4-stage pipeline, K=32 ----
#define LDA 144                  // (small-GEMM row pitch, unchanged)
#define LDA2 80                  // big-kernel stage row pitch (conflict-free for ldsm)
#define AV2 (128 * LDA2)         // 10240 bytes per variant tile
#define SV_MHI 0
#define SV_RHI (1 * AV2)
#define SV_RLO (2 * AV2)
#define SV_BHI (3 * AV2)
#define SV_BLO (4 * AV2)
#define STAGE2 (5 * AV2)         // 51200
#define BIG_SMEM (4 * STAGE2)    // 204800
#define NCH2 128                 // K-chunks of 32

__global__ __launch_bounds__(512, 1) void big_inc_mma_kernel(
    const __nv_bfloat16* __restrict__ am_s, const __nv_bfloat16* __restrict__ rh_s,
    const __nv_bfloat16* __restrict__ rl_s,
    const __nv_bfloat16* __restrict__ am_t, const __nv_bfloat16* __restrict__ rh_t,
    const __nv_bfloat16* __restrict__ rl_t,
    const __nv_bfloat16* __restrict__ bhi_s, const __nv_bfloat16* __restrict__ blo_s,
    const __nv_bfloat16* __restrict__ bhi_t, const __nv_bfloat16* __restrict__ blo_t,
    const float* __restrict__ cur,
    const float* __restrict__ master_s, const float* __restrict__ master_t,
    const float* __restrict__ deg_s, const float* __restrict__ deg_t,
    float* __restrict__ emb_s, float* __restrict__ emb_t,
    float* __restrict__ sqpart_s, float* __restrict__ sqpart_t)
{
    extern __shared__ char smem[];
    const int tid = threadIdx.x;
    const int wid = tid >> 5;        // 0..15
    const int lane = tid & 31;
    const int cb = blockIdx.x;
    const int rb = blockIdx.y;
    const bool spatial = (blockIdx.z == 0);

    const __nv_bfloat16* am = spatial ? am_s : am_t;
    const __nv_bfloat16* rh = spatial ? rh_s : rh_t;
    const __nv_bfloat16* rl = spatial ? rl_s : rl_t;
    const __nv_bfloat16* bh = spatial ? bhi_s : bhi_t;
    const __nv_bfloat16* bl = spatial ? blo_s : blo_t;
    const float* master = spatial ? master_s : master_t;
    const float* deg    = spatial ? deg_s : deg_t;
    float* emb          = spatial ? emb_s : emb_t;
    float* sqpart       = spatial ? sqpart_s : sqpart_t;

    const uint32_t sb = smem_to_u32(smem);

    // warp tile: 16 (M) x 64 (N); 8 M-groups x 2 N-groups
    const int warp_m = (wid & 7) * 16;
    const int warp_n = (wid >> 3) * 64;

    float craw[8][4] = {};
    float crel[8][4] = {};

    // A: 3 variants x 128 rows x 4 x 16B = 1536 cp ops
    auto load_a = [&](int ch, int stage_off) {
#pragma unroll
        for (int i = 0; i < 3; i++) {
            int e = tid + 512 * i;           // 0..1535
            int var = e >> 9;
            int rem = e & 511;
            int r = rem >> 2, k8 = rem & 3;
            const __nv_bfloat16* src =
                (var == 0 ? am : var == 1 ? rh : rl)
                + (size_t)(rb * 128 + r) * NN + ch * 32 + k8 * 8;
            uint32_t dst = sb + stage_off + var * AV2 + r * LDA2 + k8 * 16;
            cpa16(dst, src);
        }
    };

    // B: 2 variants x 128 rows x 4 = 1024 cp ops
    auto load_b = [&](int ch, int stage_off) {
#pragma unroll
        for (int i = 0; i < 2; i++) {
            int e = tid + 512 * i;           // 0..1023
            int var = e >> 9;
            int rem = e & 511;
            int n = rem >> 2, k8 = rem & 3;
            const __nv_bfloat16* src =
                (var ? bl : bh) + (size_t)(cb * 128 + n) * NN + ch * 32 + k8 * 8;
            uint32_t dst = sb + stage_off + (var ? SV_BLO : SV_BHI) + n * LDA2 + k8 * 16;
            cpa16(dst, src);
        }
    };

    auto do_mma = [&](int stage_off) {
        const uint32_t stb = sb + stage_off;
        const int ar = warp_m + (lane & 15);
        const int br = (lane & 7) + ((lane >> 4) & 1) * 8;
#pragma unroll
        for (int ks = 0; ks < 2; ks++) {
            const int acol = ks * 32 + (lane >> 4) * 16;
            const int bcol = ks * 32 + ((lane >> 3) & 1) * 16;
            uint32_t amr[4], arh[4], arl[4];
            {
                uint32_t ao = stb + ar * LDA2 + acol;
                ldsm4(amr[0], amr[1], amr[2], amr[3], ao + SV_MHI);
                ldsm4(arh[0], arh[1], arh[2], arh[3], ao + SV_RHI);
                ldsm4(arl[0], arl[1], arl[2], arl[3], ao + SV_RLO);
            }
#pragma unroll
            for (int p = 0; p < 4; p++) {
                uint32_t bo = stb + (warp_n + p * 16 + br) * LDA2 + bcol;
                uint32_t bh0[2], bh1[2], bl0[2], bl1[2];
                {
                    uint32_t r0, r1, r2, r3;
                    ldsm4(r0, r1, r2, r3, bo + SV_BHI);
                    bh0[0] = r0; bh0[1] = r1; bh1[0] = r2; bh1[1] = r3;
                    ldsm4(r0, r1, r2, r3, bo + SV_BLO);
                    bl0[0] = r0; bl0[1] = r1; bl1[0] = r2; bl1[1] = r3;
                }
                mma16816(craw[p * 2],     amr, bh0);
                mma16816(crel[p * 2],     arh, bh0);
                mma16816(crel[p * 2],     arh, bl0);
                mma16816(crel[p * 2],     arl, bh0);
                mma16816(craw[p * 2 + 1], amr, bh1);
                mma16816(crel[p * 2 + 1], arh, bh1);
                mma16816(crel[p * 2 + 1], arh, bl1);
                mma16816(crel[p * 2 + 1], arl, bh1);
            }
        }
    };

    // ---- prologue: fill 3 stages ----
    load_a(0, 0 * STAGE2); load_b(0, 0 * STAGE2); CP_COMMIT();
    load_a(1, 1 * STAGE2); load_b(1, 1 * STAGE2); CP_COMMIT();
    load_a(2, 2 * STAGE2); load_b(2, 2 * STAGE2); CP_COMMIT();

    // ---- main loop: 4-stage, wait_group 2 (stage ch ready when <=2 newer pending) ----
    for (int ch = 0; ch < NCH2; ch++) {
        CP_WAIT2();
        __syncthreads();
        if (ch + 3 < NCH2) {
            const int sn = ((ch + 3) & 3) * STAGE2;
            load_a(ch + 3, sn);
            load_b(ch + 3, sn);
        }
        CP_COMMIT();          // always commit (possibly empty) to keep group count exact
        do_mma((ch & 3) * STAGE2);
        // no bottom sync — next iteration's top sync protects the reused stage
    }

    float sq = 0.f;
#pragma unroll
    for (int half = 0; half < 2; half++) {
        const int m = rb * 128 + warp_m + (lane >> 2) + half * 8;
        const float invd = 1.0f / __ldg(&deg[m]);
#pragma unroll
        for (int nt = 0; nt < 8; nt++) {
            const int n = cb * 128 + warp_n + nt * 8 + (lane & 3) * 2;
            const size_t off = (size_t)m * DD + n;
            float2 ms = *(const float2*)&master[off];
            float2 cv = *(const float2*)&cur[off];
            float d0 = ms.x - craw[nt][half * 2 + 0];
            float d1 = ms.y - craw[nt][half * 2 + 1];
            sq = fmaf(d0, d0, fmaf(d1, d1, sq));
            float2 o;
            o.x = (crel[nt][half * 2 + 0] + cv.x) * invd;
            o.y = (crel[nt][half * 2 + 1] + cv.y) * invd;
            *(float2*)&emb[off] = o;
        }
    }
    __syncthreads();
    float tot = block_sum_512(sq, (float*)smem);
    if (tid == 0) sqpart[rb * 2 + cb] = tot;
}

// ---------------- small GEMM via mma: C[64,256] = A[64,256] @ Bsplit^T ----------------
#define FA_HI 0
#define FA_LO 9216              // 64*144
#define FB_HI 18432
#define FB_LO 55296             // 18432 + 256*144
#define FEA_SMEM 92160          // 55296 + 36864

__device__ __forceinline__ void gemm64_mma_body(
    const float* __restrict__ A, const __nv_bfloat16* __restrict__ Bhi,
    const __nv_bfloat16* __restrict__ Blo, const float* __restrict__ bias,
    float* __restrict__ C, int row0, bool relubias, char* smem)
{
    const int tid = threadIdx.x, wid = tid >> 5, lane = tid & 31;
    const uint32_t sb = smem_to_u32(smem);
    const int warp_m = (wid & 1) * 32;
    const int warp_n = (wid >> 1) * 64;
    float acc[2][8][4] = {};
    const int arow = tid >> 2, kq = (tid & 3) * 16;

    for (int chk = 0; chk < 4; chk++) {
        const int kb = chk * 64;
#pragma unroll
        for (int i = 0; i < 16; i++) {
            int e = tid + 256 * i;
            int var = e >> 11, rem = e & 2047;
            int n = rem >> 3, k8 = rem & 7;
            const __nv_bfloat16* src = (var ? Blo : Bhi) + (size_t)n * DD + kb + k8 * 8;
            cpa16(sb + (var ? FB_LO : FB_HI) + n * LDA + k8 * 16, src);
        }
        CP_COMMIT();
        {
            float av[16];
#pragma unroll
            for (int q = 0; q < 4; q++) {
                float4 v = *(const float4*)&A[(size_t)(row0 + arow) * DD + kb + kq + q * 4];
                av[q * 4] = v.x; av[q * 4 + 1] = v.y;
                av[q * 4 + 2] = v.z; av[q * 4 + 3] = v.w;
            }
            char* ph = smem + FA_HI + arow * LDA + kq * 2;
            char* pl = smem + FA_LO + arow * LDA + kq * 2;
#pragma unroll
            for (int c = 0; c < 16; c += 8) {
                uint4 uh, ul;
#pragma unroll
                for (int j = 0; j < 4; j++) {
                    float v0 = av[c + 2 * j], v1 = av[c + 2 * j + 1];
                    __nv_bfloat16 h0 = __float2bfloat16(v0), h1 = __float2bfloat16(v1);
                    __nv_bfloat16 l0 = __float2bfloat16(v0 - __bfloat162float(h0));
                    __nv_bfloat16 l1 = __float2bfloat16(v1 - __bfloat162float(h1));
                    __nv_bfloat162 hp = __halves2bfloat162(h0, h1);
                    __nv_bfloat162 lp = __halves2bfloat162(l0, l1);
                    ((uint32_t*)&uh)[j] = *(uint32_t*)&hp;
                    ((uint32_t*)&ul)[j] = *(uint32_t*)&lp;
                }
                *(uint4*)(ph + c * 2) = uh;
                *(uint4*)(pl + c * 2) = ul;
            }
        }
        CP_WAIT0();
        __syncthreads();
        const int ar = warp_m + (lane & 15);
        const int br = (lane & 7) + ((lane >> 4) & 1) * 8;
#pragma unroll
        for (int ks = 0; ks < 4; ks++) {
            const int acol = ks * 32 + (lane >> 4) * 16;
            const int bcol = ks * 32 + ((lane >> 3) & 1) * 16;
            uint32_t ah[2][4], al[2][4];
#pragma unroll
            for (int mt = 0; mt < 2; mt++) {
                uint32_t ao = sb + (ar + mt * 16) * LDA + acol;
                ldsm4(ah[mt][0], ah[mt][1], ah[mt][2], ah[mt][3], ao + FA_HI);
                ldsm4(al[mt][0], al[mt][1], al[mt][2], al[mt][3], ao + FA_LO);
            }
            uint32_t bhh[8][2], blr[8][2];
#pragma unroll
            for (int p = 0; p < 4; p++) {
                uint32_t bo = sb + (warp_n + p * 16 + br) * LDA + bcol;
                uint32_t r0, r1, r2, r3;
                ldsm4(r0, r1, r2, r3, bo + FB_HI);
                bhh[p * 2][0] = r0; bhh[p * 2][1] = r1;
                bhh[p * 2 + 1][0] = r2; bhh[p * 2 + 1][1] = r3;
                ldsm4(r0, r1, r2, r3, bo + FB_LO);
                blr[p * 2][0] = r0; blr[p * 2][1] = r1;
                blr[p * 2 + 1][0] = r2; blr[p * 2 + 1][1] = r3;
            }
#pragma unroll
            for (int mt = 0; mt < 2; mt++)
#pragma unroll
                for (int nt = 0; nt < 8; nt++) {
                    mma16816(acc[mt][nt], ah[mt], bhh[nt]);
                    mma16816(acc[mt][nt], ah[mt], blr[nt]);
                    mma16816(acc[mt][nt], al[mt], bhh[nt]);
                }
        }
        __syncthreads();
    }
#pragma unroll
    for (int mt = 0; mt < 2; mt++)
#pragma unroll
        for (int half = 0; half < 2; half++) {
            int m = row0 + warp_m + mt * 16 + (lane >> 2) + half * 8;
#pragma unroll
            for (int nt = 0; nt < 8; nt++) {
                int n = warp_n + nt * 8 + (lane & 3) * 2;
                float v0 = acc[mt][nt][half * 2 + 0];
                float v1 = acc[mt][nt][half * 2 + 1];
                if (relubias) {
                    v0 = fmaxf(v0 + __ldg(&bias[n + 0]), 0.f);
                    v1 = fmaxf(v1 + __ldg(&bias[n + 1]), 0.f);
                }
                *(float2*)&C[(size_t)m * DD + n] = make_float2(v0, v1);
            }
        }
}

// projA: z=0 master_s (w0), z=1 master_t (w1), z=2 node_fea (w2); A=cur
__global__ __launch_bounds__(256) void projA_kernel(
    const float* __restrict__ cur,
    const __nv_bfloat16* __restrict__ whi, const __nv_bfloat16* __restrict__ wlo,
    float* __restrict__ master_s, float* __restrict__ master_t, float* __restrict__ node_fea)
{
    extern __shared__ char smem[];
    const int z = blockIdx.y;
    const __nv_bfloat16* bhp = whi + (size_t)z * DD * DD;
    const __nv_bfloat16* blp = wlo + (size_t)z * DD * DD;
    float* C = (z == 0) ? master_s : (z == 1) ? master_t : node_fea;
    gemm64_mma_body(cur, bhp, blp, nullptr, C, blockIdx.x * 64, false, smem);
}

// projB: z=0 spa_fea (w3, A=spa_emb), z=1 tmp_fea (w4, A=tmp_emb)
__global__ __launch_bounds__(256) void projB_kernel(
    const float* __restrict__ spa_emb, const float* __restrict__ tmp_emb,
    const __nv_bfloat16* __restrict__ whi, const __nv_bfloat16* __restrict__ wlo,
    float* __restrict__ spa_fea, float* __restrict__ tmp_fea)
{
    extern __shared__ char smem[];
    const int z = blockIdx.y;
    const float* A = z ? tmp_emb : spa_emb;
    const __nv_bfloat16* bhp = whi + (size_t)(3 + z) * DD * DD;
    const __nv_bfloat16* blp = wlo + (size_t)(3 + z) * DD * DD;
    float* C = z ? tmp_fea : spa_fea;
    gemm64_mma_body(A, bhp, blp, nullptr, C, blockIdx.x * 64, false, smem);
}

__global__ __launch_bounds__(256) void final_kernel(
    const float* __restrict__ val,
    const __nv_bfloat16* __restrict__ whi, const __nv_bfloat16* __restrict__ wlo,
    const float* __restrict__ bias, float* __restrict__ out)
{
    extern __shared__ char smem[];
    gemm64_mma_body(val, whi + (size_t)5 * DD * DD, wlo + (size_t)5 * DD * DD,
                    bias, out, blockIdx.x * 64, true, smem);
}

// ---------------- attention + val ----------------
__global__ __launch_bounds__(256) void attn_val_kernel() {
    __shared__ float red[256];
    int i = blockIdx.x;
    int d = threadIdx.x;
    size_t idx = (size_t)i * DD + d;
    float nf = g_node_fea[idx];
    float sf = g_spa_fea[idx];
    float tf = g_tmp_fea[idx];
    float ds = block_sum_256(sf * nf, red);
    float dt = block_sum_256(tf * nf, red);
    float as = ds * 0.0625f;  // 1/sqrt(256)
    float at = dt * 0.0625f;
    g_val[idx] = as * sf + at * tf;
}

// ---------------- finalize loss ----------------
__global__ __launch_bounds__(256) void finalize_kernel(float* __restrict__ out, int out_size) {
    __shared__ float red[256];
    int t = threadIdx.x;
    float abs_s = 0.f, sq_s = 0.f, abs_t = 0.f, sq_t = 0.f;
    for (int i = t; i < NN; i += 256) {
        abs_s += g_rowabs_s[i];
        sq_s  += g_rowsq_s[i];
        abs_t += g_rowabs_t[i];
        sq_t  += g_rowsq_t[i];
    }
    float d_s = (t < 64) ? g_sqpart_s[t] : 0.f;
    float d_t = (t < 64) ? g_sqpart_t[t] : 0.f;
    abs_s = block_sum_256(abs_s, red);
    sq_s  = block_sum_256(sq_s,  red);
    abs_t = block_sum_256(abs_t, red);
    sq_t  = block_sum_256(sq_t,  red);
    d_s   = block_sum_256(d_s,   red);
    d_t   = block_sum_256(d_t,   red);
    float loss = 0.2f * sqrtf(d_s) + abs_s + 0.001f * sqrtf(sq_s)
               + 0.2f * sqrtf(d_t) + abs_t + 0.001f * sqrtf(sq_t);
    for (int idx = NN * DD + t; idx < out_size; idx += 256)
        out[idx] = loss;
}

// ---------------- launch ----------------
extern "C" void kernel_launch(void* const* d_in, const int* in_sizes, int n_in,
                              void* d_out, int out_size) {
    const float* cur           = (const float*)d_in[0];
    const float* pre           = (const float*)d_in[1];
    const float* r_proj_s      = (const float*)d_in[2];
    const float* inc_s         = (const float*)d_in[3];
    const float* r_proj_t      = (const float*)d_in[4];
    const float* inc_t         = (const float*)d_in[5];
    const float* node_proj     = (const float*)d_in[6];
    const float* spa_edge_proj = (const float*)d_in[7];
    const float* tmp_edge_proj = (const float*)d_in[8];
    const float* theta_w       = (const float*)d_in[9];
    const float* theta_b       = (const float*)d_in[10];
    float* out = (float*)d_out;

    float *p_spa_emb, *p_tmp_emb, *p_node_fea, *p_spa_fea, *p_tmp_fea, *p_val;
    float *p_master_s, *p_master_t;
    float *p_deg_s, *p_deg_t, *p_rowabs_s, *p_rowsq_s, *p_rowabs_t, *p_rowsq_t;
    float *p_sqpart_s, *p_sqpart_t;
    __nv_bfloat16 *p_bhi_s, *p_blo_s, *p_bhi_t, *p_blo_t;
    __nv_bfloat16 *p_am_s, *p_rh_s, *p_rl_s, *p_am_t, *p_rh_t, *p_rl_t, *p_whi, *p_wlo;
    cudaGetSymbolAddress((void**)&p_spa_emb,  g_spa_emb);
    cudaGetSymbolAddress((void**)&p_tmp_emb,  g_tmp_emb);
    cudaGetSymbolAddress((void**)&p_node_fea, g_node_fea);
    cudaGetSymbolAddress((void**)&p_spa_fea,  g_spa_fea);
    cudaGetSymbolAddress((void**)&p_tmp_fea,  g_tmp_fea);
    cudaGetSymbolAddress((void**)&p_val,      g_val);
    cudaGetSymbolAddress((void**)&p_master_s, g_master_s);
    cudaGetSymbolAddress((void**)&p_master_t, g_master_t);
    cudaGetSymbolAddress((void**)&p_deg_s,    g_deg_s);
    cudaGetSymbolAddress((void**)&p_deg_t,    g_deg_t);
    cudaGetSymbolAddress((void**)&p_rowabs_s, g_rowabs_s);
    cudaGetSymbolAddress((void**)&p_rowsq_s,  g_rowsq_s);
    cudaGetSymbolAddress((void**)&p_rowabs_t, g_rowabs_t);
    cudaGetSymbolAddress((void**)&p_rowsq_t,  g_rowsq_t);
    cudaGetSymbolAddress((void**)&p_sqpart_s, g_sqpart_s);
    cudaGetSymbolAddress((void**)&p_sqpart_t, g_sqpart_t);
    cudaGetSymbolAddress((void**)&p_bhi_s,    g_bhi_s);
    cudaGetSymbolAddress((void**)&p_blo_s,    g_blo_s);
    cudaGetSymbolAddress((void**)&p_bhi_t,    g_bhi_t);
    cudaGetSymbolAddress((void**)&p_blo_t,    g_blo_t);
    cudaGetSymbolAddress((void**)&p_am_s,     g_am_s);
    cudaGetSymbolAddress((void**)&p_rh_s,     g_rh_s);
    cudaGetSymbolAddress((void**)&p_rl_s,     g_rl_s);
    cudaGetSymbolAddress((void**)&p_am_t,     g_am_t);
    cudaGetSymbolAddress((void**)&p_rh_t,     g_rh_t);
    cudaGetSymbolAddress((void**)&p_rl_t,     g_rl_t);
    cudaGetSymbolAddress((void**)&p_whi,      g_whi);
    cudaGetSymbolAddress((void**)&p_wlo,      g_wlo);

    static bool attr_set = false;
    static cudaStream_t s2 = nullptr;
    static cudaEvent_t evF = nullptr, evJ = nullptr;
    if (!attr_set) {
        cudaFuncSetAttribute(big_inc_mma_kernel,
                             cudaFuncAttributeMaxDynamicSharedMemorySize, BIG_SMEM);
        cudaFuncSetAttribute(projA_kernel,
                             cudaFuncAttributeMaxDynamicSharedMemorySize, FEA_SMEM);
        cudaFuncSetAttribute(projB_kernel,
                             cudaFuncAttributeMaxDynamicSharedMemorySize, FEA_SMEM);
        cudaFuncSetAttribute(final_kernel,
                             cudaFuncAttributeMaxDynamicSharedMemorySize, FEA_SMEM);
        cudaStreamCreateWithFlags(&s2, cudaStreamNonBlocking);
        cudaEventCreateWithFlags(&evF, cudaEventDisableTiming);
        cudaEventCreateWithFlags(&evJ, cudaEventDisableTiming);
        attr_set = true;
    }

    // ---- fork: presplit (DRAM-bound) on s2, concurrent with wsplit/bsplit/projA ----
    cudaEventRecord(evF, 0);
    cudaStreamWaitEvent(s2, evF, 0);
    presplit_kernel<<<dim3(NN, 2), 256, 0, s2>>>(inc_s, inc_t,
                                                 p_am_s, p_rh_s, p_rl_s,
                                                 p_am_t, p_rh_t, p_rl_t,
                                                 p_rowabs_s, p_rowsq_s, p_deg_s,
                                                 p_rowabs_t, p_rowsq_t, p_deg_t);
    cudaEventRecord(evJ, s2);

    // main stream (concurrent with presplit):
    wsplit_kernel<<<dim3(4, 4, 6), 256>>>(r_proj_s, r_proj_t, node_proj,
                                          spa_edge_proj, tmp_edge_proj, theta_w,
                                          p_whi, p_wlo);
    bsplit_kernel<<<dim3(NN / 64, DD / 64, 2), 256>>>(cur, pre,
                                                      p_bhi_s, p_blo_s, p_bhi_t, p_blo_t);
    projA_kernel<<<dim3(NN / 64, 3), 256, FEA_SMEM>>>(cur, p_whi, p_wlo,
                                                      p_master_s, p_master_t, p_node_fea);

    // join: big kernel needs presplit's outputs
    cudaStreamWaitEvent(0, evJ, 0);

    // BIG tensor-core fused incidence GEMMs (512 threads / 16 warps, 4-stage pipe)
    big_inc_mma_kernel<<<dim3(2, 32, 2), 512, BIG_SMEM>>>(
        p_am_s, p_rh_s, p_rl_s, p_am_t, p_rh_t, p_rl_t,
        p_bhi_s, p_blo_s, p_bhi_t, p_blo_t, cur,
        p_master_s, p_master_t, p_deg_s, p_deg_t,
        p_spa_emb, p_tmp_emb, p_sqpart_s, p_sqpart_t);

    // spa/tmp feature projections (mma, one launch)
    projB_kernel<<<dim3(NN / 64, 2), 256, FEA_SMEM>>>(p_spa_emb, p_tmp_emb,
                                                      p_whi, p_wlo, p_spa_fea, p_tmp_fea);

    // attention + val
    attn_val_kernel<<<NN, 256>>>();

    // node_emb = relu(val @ theta_w^T + theta_b)  -> d_out[0 .. N*D)
    final_kernel<<<dim3(NN / 64), 256, FEA_SMEM>>>(p_val, p_whi, p_wlo, theta_b, out);

    // loss scalar -> d_out[N*D ...]
    finalize_kernel<<<1, 256>>>(out, out_size);
}

// round 14
// speedup vs baseline: 1.6043x; 1.6043x over previous
#include <cuda_runtime.h>
#include <cuda_bf16.h>
#include <math.h>
#include <stdint.h>

#define NN 4096
#define DD 256

// ---------------- scratch (device globals; no allocation allowed) ----------------
__device__ float g_spa_emb[NN * DD];
__device__ float g_tmp_emb[NN * DD];
__device__ float g_node_fea[NN * DD];
__device__ float g_spa_fea[NN * DD];
__device__ float g_tmp_fea[NN * DD];
__device__ float g_val[NN * DD];
__device__ float g_master_s[NN * DD];
__device__ float g_master_t[NN * DD];
__device__ float g_deg_s[NN];
__device__ float g_deg_t[NN];
__device__ float g_rowabs_s[NN];
__device__ float g_rowsq_s[NN];
__device__ float g_rowabs_t[NN];
__device__ float g_rowsq_t[NN];
__device__ float g_sqpart_s[64];
__device__ float g_sqpart_t[64];
// pre-split, pre-transposed X: [D][N] bf16 hi/lo
__device__ __nv_bfloat16 g_bhi_s[DD * NN];
__device__ __nv_bfloat16 g_blo_s[DD * NN];
__device__ __nv_bfloat16 g_bhi_t[DD * NN];
__device__ __nv_bfloat16 g_blo_t[DD * NN];
// pre-split incidence matrices (scattered, zero-diag for spatial), [N][N] bf16
__device__ __nv_bfloat16 g_am_s[(size_t)NN * NN];   // raw
__device__ __nv_bfloat16 g_rh_s[(size_t)NN * NN];   // relu hi
__device__ __nv_bfloat16 g_rl_s[(size_t)NN * NN];   // relu lo
__device__ __nv_bfloat16 g_am_t[(size_t)NN * NN];
__device__ __nv_bfloat16 g_rh_t[(size_t)NN * NN];
__device__ __nv_bfloat16 g_rl_t[(size_t)NN * NN];
// pre-split weights, K-major [n][k]: 0:rpsT 1:rptT 2:nodeT 3:spaT 4:tmpT 5:theta direct
__device__ __nv_bfloat16 g_whi[6 * DD * DD];
__device__ __nv_bfloat16 g_wlo[6 * DD * DD];

// ---------------- PTX helpers (sm_80-baseline only) ----------------
__device__ __forceinline__ uint32_t smem_to_u32(const void* p) {
    uint32_t a;
    asm("{ .reg .u64 t; cvta.to.shared.u64 t, %1; cvt.u32.u64 %0, t; }" : "=r"(a) : "l"(p));
    return a;
}

__device__ __forceinline__ void ldsm4(uint32_t& r0, uint32_t& r1, uint32_t& r2, uint32_t& r3,
                                      uint32_t addr) {
    asm volatile("ldmatrix.sync.aligned.m8n8.x4.shared.b16 {%0,%1,%2,%3}, [%4];"
                 : "=r"(r0), "=r"(r1), "=r"(r2), "=r"(r3) : "r"(addr));
}

__device__ __forceinline__ void mma16816(float* c, const uint32_t* a, const uint32_t* b) {
    asm volatile("mma.sync.aligned.m16n8k16.row.col.f32.bf16.bf16.f32 "
                 "{%0,%1,%2,%3}, {%4,%5,%6,%7}, {%8,%9}, {%0,%1,%2,%3};"
                 : "+f"(c[0]), "+f"(c[1]), "+f"(c[2]), "+f"(c[3])
                 : "r"(a[0]), "r"(a[1]), "r"(a[2]), "r"(a[3]), "r"(b[0]), "r"(b[1]));
}

__device__ __forceinline__ void cpa16(uint32_t dst, const void* src) {
    asm volatile("cp.async.cg.shared.global [%0], [%1], 16;" :: "r"(dst), "l"(src));
}
#define CP_COMMIT() asm volatile("cp.async.commit_group;" ::: "memory")
#define CP_WAIT0()  asm volatile("cp.async.wait_group 0;" ::: "memory")

// ---------------- helpers ----------------
__device__ __forceinline__ float block_sum_256(float v, float* red) {
    int t = threadIdx.x;
    red[t] = v;
    __syncthreads();
#pragma unroll
    for (int s = 128; s > 0; s >>= 1) {
        if (t < s) red[t] += red[t + s];
        __syncthreads();
    }
    float r = red[0];
    __syncthreads();
    return r;
}

__device__ __forceinline__ float block_sum_512(float v, float* red) {
    int t = threadIdx.x;
    red[t] = v;
    __syncthreads();
#pragma unroll
    for (int s = 256; s > 0; s >>= 1) {
        if (t < s) red[t] += red[t + s];
        __syncthreads();
    }
    float r = red[0];
    __syncthreads();
    return r;
}

// ---------------- K0a: incidence pre-split (+ fused row reductions) ----------------
__global__ __launch_bounds__(256) void presplit_kernel(
    const float* __restrict__ inc_s, const float* __restrict__ inc_t,
    __nv_bfloat16* __restrict__ am_s, __nv_bfloat16* __restrict__ rh_s,
    __nv_bfloat16* __restrict__ rl_s,
    __nv_bfloat16* __restrict__ am_t, __nv_bfloat16* __restrict__ rh_t,
    __nv_bfloat16* __restrict__ rl_t,
    float* __restrict__ rowabs_s, float* __restrict__ rowsq_s, float* __restrict__ deg_s,
    float* __restrict__ rowabs_t, float* __restrict__ rowsq_t, float* __restrict__ deg_t)
{
    __shared__ float red[256];
    const int i = blockIdx.x;
    const bool sp = (blockIdx.y == 0);
    const float* inc = sp ? inc_s : inc_t;
    __nv_bfloat16* am = sp ? am_s : am_t;
    __nv_bfloat16* rh = sp ? rh_s : rh_t;
    __nv_bfloat16* rl = sp ? rl_s : rl_t;
    const int t = threadIdx.x;
    const int j0 = t * 16;

    float v[16];
    if (sp) {
        const float* rp = inc + (size_t)i * (NN - 1);
#pragma unroll
        for (int c = 0; c < 16; c++) {
            int j = j0 + c;
            v[c] = (j == i) ? 0.f : __ldg(&rp[j < i ? j : j - 1]);
        }
    } else {
        const float* rp = inc + (size_t)i * NN + j0;
#pragma unroll
        for (int c = 0; c < 16; c += 4) {
            float4 q = *(const float4*)&rp[c];
            v[c] = q.x; v[c + 1] = q.y; v[c + 2] = q.z; v[c + 3] = q.w;
        }
    }

    float sa = 0.f, ss = 0.f, sd = 0.f;
    uint4 um[2], uh[2], ul[2];
#pragma unroll
    for (int c = 0; c < 16; c += 2) {
        float v0 = v[c], v1 = v[c + 1];
        sa += fabsf(v0) + fabsf(v1);
        ss = fmaf(v0, v0, fmaf(v1, v1, ss));
        float r0 = fmaxf(v0, 0.f), r1 = fmaxf(v1, 0.f);
        sd += r0 + r1;
        __nv_bfloat16 h0 = __float2bfloat16(r0), h1 = __float2bfloat16(r1);
        __nv_bfloat16 l0 = __float2bfloat16(r0 - __bfloat162float(h0));
        __nv_bfloat16 l1 = __float2bfloat16(r1 - __bfloat162float(h1));
        __nv_bfloat162 mp = __halves2bfloat162(__float2bfloat16(v0), __float2bfloat16(v1));
        __nv_bfloat162 hp = __halves2bfloat162(h0, h1);
        __nv_bfloat162 lp = __halves2bfloat162(l0, l1);
        ((uint32_t*)um)[c >> 1] = *(uint32_t*)&mp;
        ((uint32_t*)uh)[c >> 1] = *(uint32_t*)&hp;
        ((uint32_t*)ul)[c >> 1] = *(uint32_t*)&lp;
    }
    size_t o = (size_t)i * NN + j0;
    *(uint4*)&am[o] = um[0]; *(uint4*)&am[o + 8] = um[1];
    *(uint4*)&rh[o] = uh[0]; *(uint4*)&rh[o + 8] = uh[1];
    *(uint4*)&rl[o] = ul[0]; *(uint4*)&rl[o + 8] = ul[1];

    sa = block_sum_256(sa, red);
    ss = block_sum_256(ss, red);
    sd = block_sum_256(sd, red);
    if (t == 0) {
        if (sp) { rowabs_s[i] = sa; rowsq_s[i] = ss; deg_s[i] = sd + 1.0f; }
        else    { rowabs_t[i] = sa; rowsq_t[i] = ss; deg_t[i] = sd + 1.0f; }
    }
}

// ---------------- K0bc: MERGED weight-split (96 blocks) + X-split (512 blocks) --------
__global__ __launch_bounds__(256) void wbsplit_kernel(
    const float* __restrict__ cur, const float* __restrict__ pre,
    const float* __restrict__ rps, const float* __restrict__ rpt,
    const float* __restrict__ np, const float* __restrict__ sp,
    const float* __restrict__ tp, const float* __restrict__ th,
    __nv_bfloat16* __restrict__ whi, __nv_bfloat16* __restrict__ wlo,
    __nv_bfloat16* __restrict__ hs, __nv_bfloat16* __restrict__ ls,
    __nv_bfloat16* __restrict__ ht, __nv_bfloat16* __restrict__ lt)
{
    __shared__ float tile[64][68];
    const int bid = blockIdx.x;
    const int tid = threadIdx.x;

    if (bid < 96) {
        // ---- wsplit: z = bid/16, y = (bid%16)/4, x = bid%4 ----
        const int z = bid >> 4, by = (bid >> 2) & 3, bx = bid & 3;
        const float* W = (z == 0) ? rps : (z == 1) ? rpt : (z == 2) ? np
                        : (z == 3) ? sp : (z == 4) ? tp : th;
        const bool tr = (z < 5);
        const int r0 = by * 64, c0 = bx * 64;
#pragma unroll
        for (int t = 0; t < 4; t++) {
            int q = tid + 256 * t;
            int rr = q >> 4, c4 = (q & 15) * 4;
            float4 v = *(const float4*)&W[(size_t)(r0 + rr) * DD + c0 + c4];
            tile[rr][c4 + 0] = v.x; tile[rr][c4 + 1] = v.y;
            tile[rr][c4 + 2] = v.z; tile[rr][c4 + 3] = v.w;
        }
        __syncthreads();
        __nv_bfloat16* hi = whi + (size_t)z * DD * DD;
        __nv_bfloat16* lo = wlo + (size_t)z * DD * DD;
#pragma unroll
        for (int t = 0; t < 4; t++) {
            int q = tid + 256 * t;
            int rr = q >> 4, c4 = (q & 15) * 4;
            float v[4];
            size_t o;
            if (tr) {
#pragma unroll
                for (int j = 0; j < 4; j++) v[j] = tile[c4 + j][rr];
                o = (size_t)(c0 + rr) * DD + r0 + c4;
            } else {
#pragma unroll
                for (int j = 0; j < 4; j++) v[j] = tile[rr][c4 + j];
                o = (size_t)(r0 + rr) * DD + c0 + c4;
            }
            __nv_bfloat16 h[4], l[4];
#pragma unroll
            for (int j = 0; j < 4; j++) {
                h[j] = __float2bfloat16(v[j]);
                l[j] = __float2bfloat16(v[j] - __bfloat162float(h[j]));
            }
            *(__nv_bfloat162*)&hi[o]     = __halves2bfloat162(h[0], h[1]);
            *(__nv_bfloat162*)&hi[o + 2] = __halves2bfloat162(h[2], h[3]);
            *(__nv_bfloat162*)&lo[o]     = __halves2bfloat162(l[0], l[1]);
            *(__nv_bfloat162*)&lo[o + 2] = __halves2bfloat162(l[2], l[3]);
        }
        return;
    }
    // ---- bsplit: r = bid-96; x=r%64, y=(r/64)%4, z=r/256 ----
    {
        const int r = bid - 96;
        const int j0 = (r & 63) * 64;
        const int d0 = ((r >> 6) & 3) * 64;
        const int z = r >> 8;
        const float* X = z ? pre : cur;
        __nv_bfloat16* hi = z ? ht : hs;
        __nv_bfloat16* lo = z ? lt : ls;
#pragma unroll
        for (int t = 0; t < 4; t++) {
            int idx = tid + 256 * t;
            int jj = idx >> 4, c4 = (idx & 15) * 4;
            float4 v = *(const float4*)&X[(size_t)(j0 + jj) * DD + d0 + c4];
            tile[jj][c4 + 0] = v.x; tile[jj][c4 + 1] = v.y;
            tile[jj][c4 + 2] = v.z; tile[jj][c4 + 3] = v.w;
        }
        __syncthreads();
#pragma unroll
        for (int t = 0; t < 4; t++) {
            int idx = tid + 256 * t;
            int dd = idx >> 4, q = (idx & 15) * 4;
            __nv_bfloat16 h[4], l[4];
#pragma unroll
            for (int k = 0; k < 4; k++) {
                float v = tile[q + k][dd];
                h[k] = __float2bfloat16(v);
                l[k] = __float2bfloat16(v - __bfloat162float(h[k]));
            }
            size_t o = (size_t)(d0 + dd) * NN + j0 + q;
            *(__nv_bfloat162*)&hi[o]     = __halves2bfloat162(h[0], h[1]);
            *(__nv_bfloat162*)&hi[o + 2] = __halves2bfloat162(h[2], h[3]);
            *(__nv_bfloat162*)&lo[o]     = __halves2bfloat162(l[0], l[1]);
            *(__nv_bfloat162*)&lo[o + 2] = __halves2bfloat162(l[2], l[3]);
        }
    }
}

// ---------------- BIG: mma.sync bf16 fused incidence GEMM — R12 version ----------------
#define LDA 144
#define AVAR (128 * LDA)        // 18432 bytes per variant tile
#define ST_MHI 0
#define ST_RHI (1 * AVAR)
#define ST_RLO (2 * AVAR)
#define ST_BHI (3 * AVAR)
#define ST_BLO (4 * AVAR)
#define STAGE  (5 * AVAR)       // 92160
#define BIG_SMEM (2 * STAGE)    // 184320
#define NCH 64

__global__ __launch_bounds__(512, 1) void big_inc_mma_kernel(
    const __nv_bfloat16* __restrict__ am_s, const __nv_bfloat16* __restrict__ rh_s,
    const __nv_bfloat16* __restrict__ rl_s,
    const __nv_bfloat16* __restrict__ am_t, const __nv_bfloat16* __restrict__ rh_t,
    const __nv_bfloat16* __restrict__ rl_t,
    const __nv_bfloat16* __restrict__ bhi_s, const __nv_bfloat16* __restrict__ blo_s,
    const __nv_bfloat16* __restrict__ bhi_t, const __nv_bfloat16* __restrict__ blo_t,
    const float* __restrict__ cur,
    const float* __restrict__ master_s, const float* __restrict__ master_t,
    const float* __restrict__ deg_s, const float* __restrict__ deg_t,
    float* __restrict__ emb_s, float* __restrict__ emb_t,
    float* __restrict__ sqpart_s, float* __restrict__ sqpart_t)
{
    extern __shared__ char smem[];
    const int tid = threadIdx.x;
    const int wid = tid >> 5;        // 0..15
    const int lane = tid & 31;
    const int cb = blockIdx.x;
    const int rb = blockIdx.y;
    const bool spatial = (blockIdx.z == 0);

    const __nv_bfloat16* am = spatial ? am_s : am_t;
    const __nv_bfloat16* rh = spatial ? rh_s : rh_t;
    const __nv_bfloat16* rl = spatial ? rl_s : rl_t;
    const __nv_bfloat16* bh = spatial ? bhi_s : bhi_t;
    const __nv_bfloat16* bl = spatial ? blo_s : blo_t;
    const float* master = spatial ? master_s : master_t;
    const float* deg    = spatial ? deg_s : deg_t;
    float* emb          = spatial ? emb_s : emb_t;
    float* sqpart       = spatial ? sqpart_s : sqpart_t;

    const uint32_t sb = smem_to_u32(smem);

    // warp tile: 16 (M) x 64 (N); 8 M-groups x 2 N-groups
    const int warp_m = (wid & 7) * 16;
    const int warp_n = (wid >> 3) * 64;

    float craw[8][4] = {};
    float crel[8][4] = {};

    auto load_a = [&](int ch, int stage_off) {
#pragma unroll
        for (int i = 0; i < 6; i++) {
            int e = tid + 512 * i;           // 0..3071
            int var = e >> 10;
            int rem = e & 1023;
            int r = rem >> 3, k8 = rem & 7;
            const __nv_bfloat16* src =
                (var == 0 ? am : var == 1 ? rh : rl)
                + (size_t)(rb * 128 + r) * NN + ch * 64 + k8 * 8;
            uint32_t dst = sb + stage_off
                + (var == 0 ? ST_MHI : var == 1 ? ST_RHI : ST_RLO) + r * LDA + k8 * 16;
            cpa16(dst, src);
        }
    };

    auto load_b = [&](int ch, int stage_off) {
#pragma unroll
        for (int i = 0; i < 4; i++) {
            int e = tid + 512 * i;           // 0..2047
            int var = e >> 10;
            int rem = e & 1023;
            int n = rem >> 3, k8 = rem & 7;
            const __nv_bfloat16* src =
                (var ? bl : bh) + (size_t)(cb * 128 + n) * NN + ch * 64 + k8 * 8;
            uint32_t dst = sb + stage_off + (var ? ST_BLO : ST_BHI) + n * LDA + k8 * 16;
            cpa16(dst, src);
        }
    };

    auto do_mma = [&](int stage_off) {
        const uint32_t stb = sb + stage_off;
        const int ar = warp_m + (lane & 15);
        const int br = (lane & 7) + ((lane >> 4) & 1) * 8;
#pragma unroll
        for (int ks = 0; ks < 4; ks++) {
            const int acol = ks * 32 + (lane >> 4) * 16;
            const int bcol = ks * 32 + ((lane >> 3) & 1) * 16;
            uint32_t amr[4], arh[4], arl[4];
            {
                uint32_t ao = stb + ar * LDA + acol;
                ldsm4(amr[0], amr[1], amr[2], amr[3], ao + ST_MHI);
                ldsm4(arh[0], arh[1], arh[2], arh[3], ao + ST_RHI);
                ldsm4(arl[0], arl[1], arl[2], arl[3], ao + ST_RLO);
            }
#pragma unroll
            for (int p = 0; p < 4; p++) {
                uint32_t bo = stb + (warp_n + p * 16 + br) * LDA + bcol;
                uint32_t bh0[2], bh1[2], bl0[2], bl1[2];
                {
                    uint32_t r0, r1, r2, r3;
                    ldsm4(r0, r1, r2, r3, bo + ST_BHI);
                    bh0[0] = r0; bh0[1] = r1; bh1[0] = r2; bh1[1] = r3;
                    ldsm4(r0, r1, r2, r3, bo + ST_BLO);
                    bl0[0] = r0; bl0[1] = r1; bl1[0] = r2; bl1[1] = r3;
                }
                mma16816(craw[p * 2],     amr, bh0);
                mma16816(crel[p * 2],     arh, bh0);
                mma16816(crel[p * 2],     arh, bl0);
                mma16816(crel[p * 2],     arl, bh0);
                mma16816(craw[p * 2 + 1], amr, bh1);
                mma16816(crel[p * 2 + 1], arh, bh1);
                mma16816(crel[p * 2 + 1], arh, bl1);
                mma16816(crel[p * 2 + 1], arl, bh1);
            }
        }
    };

    load_a(0, 0);
    load_b(0, 0);
    CP_COMMIT();

    for (int ch = 0; ch < NCH; ch++) {
        const int so = (ch & 1) * STAGE;
        const int sn = ((ch & 1) ^ 1) * STAGE;
        CP_WAIT0();
        __syncthreads();
        if (ch + 1 < NCH) {
            load_a(ch + 1, sn);
            load_b(ch + 1, sn);
            CP_COMMIT();
        }
        do_mma(so);
        // no bottom sync — next iteration's top sync protects stage `so`
    }

    float sq = 0.f;
#pragma unroll
    for (int half = 0; half < 2; half++) {
        const int m = rb * 128 + warp_m + (lane >> 2) + half * 8;
        const float invd = 1.0f / __ldg(&deg[m]);
#pragma unroll
        for (int nt = 0; nt < 8; nt++) {
            const int n = cb * 128 + warp_n + nt * 8 + (lane & 3) * 2;
            const size_t off = (size_t)m * DD + n;
            float2 ms = *(const float2*)&master[off];
            float2 cv = *(const float2*)&cur[off];
            float d0 = ms.x - craw[nt][half * 2 + 0];
            float d1 = ms.y - craw[nt][half * 2 + 1];
            sq = fmaf(d0, d0, fmaf(d1, d1, sq));
            float2 o;
            o.x = (crel[nt][half * 2 + 0] + cv.x) * invd;
            o.y = (crel[nt][half * 2 + 1] + cv.y) * invd;
            *(float2*)&emb[off] = o;
        }
    }
    __syncthreads();
    float tot = block_sum_512(sq, (float*)smem);
    if (tid == 0) sqpart[rb * 2 + cb] = tot;
}

// ---------------- small GEMM via mma: C[64,256] = A[64,256] @ Bsplit^T ----------------
#define FA_HI 0
#define FA_LO 9216              // 64*144
#define FB_HI 18432
#define FB_LO 55296             // 18432 + 256*144
#define FEA_SMEM 92160          // 55296 + 36864

__device__ __forceinline__ void gemm64_mma_body(
    const float* __restrict__ A, const __nv_bfloat16* __restrict__ Bhi,
    const __nv_bfloat16* __restrict__ Blo, const float* __restrict__ bias,
    float* __restrict__ C, int row0, bool relubias, char* smem)
{
    const int tid = threadIdx.x, wid = tid >> 5, lane = tid & 31;
    const uint32_t sb = smem_to_u32(smem);
    const int warp_m = (wid & 1) * 32;
    const int warp_n = (wid >> 1) * 64;
    float acc[2][8][4] = {};
    const int arow = tid >> 2, kq = (tid & 3) * 16;

    for (int chk = 0; chk < 4; chk++) {
        const int kb = chk * 64;
#pragma unroll
        for (int i = 0; i < 16; i++) {
            int e = tid + 256 * i;
            int var = e >> 11, rem = e & 2047;
            int n = rem >> 3, k8 = rem & 7;
            const __nv_bfloat16* src = (var ? Blo : Bhi) + (size_t)n * DD + kb + k8 * 8;
            cpa16(sb + (var ? FB_LO : FB_HI) + n * LDA + k8 * 16, src);
        }
        CP_COMMIT();
        {
            float av[16];
#pragma unroll
            for (int q = 0; q < 4; q++) {
                float4 v = *(const float4*)&A[(size_t)(row0 + arow) * DD + kb + kq + q * 4];
                av[q * 4] = v.x; av[q * 4 + 1] = v.y;
                av[q * 4 + 2] = v.z; av[q * 4 + 3] = v.w;
            }
            char* ph = smem + FA_HI + arow * LDA + kq * 2;
            char* pl = smem + FA_LO + arow * LDA + kq * 2;
#pragma unroll
            for (int c = 0; c < 16; c += 8) {
                uint4 uh, ul;
#pragma unroll
                for (int j = 0; j < 4; j++) {
                    float v0 = av[c + 2 * j], v1 = av[c + 2 * j + 1];
                    __nv_bfloat16 h0 = __float2bfloat16(v0), h1 = __float2bfloat16(v1);
                    __nv_bfloat16 l0 = __float2bfloat16(v0 - __bfloat162float(h0));
                    __nv_bfloat16 l1 = __float2bfloat16(v1 - __bfloat162float(h1));
                    __nv_bfloat162 hp = __halves2bfloat162(h0, h1);
                    __nv_bfloat162 lp = __halves2bfloat162(l0, l1);
                    ((uint32_t*)&uh)[j] = *(uint32_t*)&hp;
                    ((uint32_t*)&ul)[j] = *(uint32_t*)&lp;
                }
                *(uint4*)(ph + c * 2) = uh;
                *(uint4*)(pl + c * 2) = ul;
            }
        }
        CP_WAIT0();
        __syncthreads();
        const int ar = warp_m + (lane & 15);
        const int br = (lane & 7) + ((lane >> 4) & 1) * 8;
#pragma unroll
        for (int ks = 0; ks < 4; ks++) {
            const int acol = ks * 32 + (lane >> 4) * 16;
            const int bcol = ks * 32 + ((lane >> 3) & 1) * 16;
            uint32_t ah[2][4], al[2][4];
#pragma unroll
            for (int mt = 0; mt < 2; mt++) {
                uint32_t ao = sb + (ar + mt * 16) * LDA + acol;
                ldsm4(ah[mt][0], ah[mt][1], ah[mt][2], ah[mt][3], ao + FA_HI);
                ldsm4(al[mt][0], al[mt][1], al[mt][2], al[mt][3], ao + FA_LO);
            }
            uint32_t bhh[8][2], blr[8][2];
#pragma unroll
            for (int p = 0; p < 4; p++) {
                uint32_t bo = sb + (warp_n + p * 16 + br) * LDA + bcol;
                uint32_t r0, r1, r2, r3;
                ldsm4(r0, r1, r2, r3, bo + FB_HI);
                bhh[p * 2][0] = r0; bhh[p * 2][1] = r1;
                bhh[p * 2 + 1][0] = r2; bhh[p * 2 + 1][1] = r3;
                ldsm4(r0, r1, r2, r3, bo + FB_LO);
                blr[p * 2][0] = r0; blr[p * 2][1] = r1;
                blr[p * 2 + 1][0] = r2; blr[p * 2 + 1][1] = r3;
            }
#pragma unroll
            for (int mt = 0; mt < 2; mt++)
#pragma unroll
                for (int nt = 0; nt < 8; nt++) {
                    mma16816(acc[mt][nt], ah[mt], bhh[nt]);
                    mma16816(acc[mt][nt], ah[mt], blr[nt]);
                    mma16816(acc[mt][nt], al[mt], bhh[nt]);
                }
        }
        __syncthreads();
    }
#pragma unroll
    for (int mt = 0; mt < 2; mt++)
#pragma unroll
        for (int half = 0; half < 2; half++) {
            int m = row0 + warp_m + mt * 16 + (lane >> 2) + half * 8;
#pragma unroll
            for (int nt = 0; nt < 8; nt++) {
                int n = warp_n + nt * 8 + (lane & 3) * 2;
                float v0 = acc[mt][nt][half * 2 + 0];
                float v1 = acc[mt][nt][half * 2 + 1];
                if (relubias) {
                    v0 = fmaxf(v0 + __ldg(&bias[n + 0]), 0.f);
                    v1 = fmaxf(v1 + __ldg(&bias[n + 1]), 0.f);
                }
                *(float2*)&C[(size_t)m * DD + n] = make_float2(v0, v1);
            }
        }
}

// projA: z=0 master_s (w0), z=1 master_t (w1), z=2 node_fea (w2); A=cur
__global__ __launch_bounds__(256) void projA_kernel(
    const float* __restrict__ cur,
    const __nv_bfloat16* __restrict__ whi, const __nv_bfloat16* __restrict__ wlo,
    float* __restrict__ master_s, float* __restrict__ master_t, float* __restrict__ node_fea)
{
    extern __shared__ char smem[];
    const int z = blockIdx.y;
    const __nv_bfloat16* bhp = whi + (size_t)z * DD * DD;
    const __nv_bfloat16* blp = wlo + (size_t)z * DD * DD;
    float* C = (z == 0) ? master_s : (z == 1) ? master_t : node_fea;
    gemm64_mma_body(cur, bhp, blp, nullptr, C, blockIdx.x * 64, false, smem);
}

// projB: z=0 spa_fea (w3, A=spa_emb), z=1 tmp_fea (w4, A=tmp_emb)
__global__ __launch_bounds__(256) void projB_kernel(
    const float* __restrict__ spa_emb, const float* __restrict__ tmp_emb,
    const __nv_bfloat16* __restrict__ whi, const __nv_bfloat16* __restrict__ wlo,
    float* __restrict__ spa_fea, float* __restrict__ tmp_fea)
{
    extern __shared__ char smem[];
    const int z = blockIdx.y;
    const float* A = z ? tmp_emb : spa_emb;
    const __nv_bfloat16* bhp = whi + (size_t)(3 + z) * DD * DD;
    const __nv_bfloat16* blp = wlo + (size_t)(3 + z) * DD * DD;
    float* C = z ? tmp_fea : spa_fea;
    gemm64_mma_body(A, bhp, blp, nullptr, C, blockIdx.x * 64, false, smem);
}

__global__ __launch_bounds__(256) void final_kernel(
    const float* __restrict__ val,
    const __nv_bfloat16* __restrict__ whi, const __nv_bfloat16* __restrict__ wlo,
    const float* __restrict__ bias, float* __restrict__ out)
{
    extern __shared__ char smem[];
    gemm64_mma_body(val, whi + (size_t)5 * DD * DD, wlo + (size_t)5 * DD * DD,
                    bias, out, blockIdx.x * 64, true, smem);
}

// ---------------- attention + val ----------------
__global__ __launch_bounds__(256) void attn_val_kernel() {
    __shared__ float red[256];
    int i = blockIdx.x;
    int d = threadIdx.x;
    size_t idx = (size_t)i * DD + d;
    float nf = g_node_fea[idx];
    float sf = g_spa_fea[idx];
    float tf = g_tmp_fea[idx];
    float ds = block_sum_256(sf * nf, red);
    float dt = block_sum_256(tf * nf, red);
    float as = ds * 0.0625f;  // 1/sqrt(256)
    float at = dt * 0.0625f;
    g_val[idx] = as * sf + at * tf;
}

// ---------------- finalize loss ----------------
__global__ __launch_bounds__(256) void finalize_kernel(float* __restrict__ out, int out_size) {
    __shared__ float red[256];
    int t = threadIdx.x;
    float abs_s = 0.f, sq_s = 0.f, abs_t = 0.f, sq_t = 0.f;
    for (int i = t; i < NN; i += 256) {
        abs_s += g_rowabs_s[i];
        sq_s  += g_rowsq_s[i];
        abs_t += g_rowabs_t[i];
        sq_t  += g_rowsq_t[i];
    }
    float d_s = (t < 64) ? g_sqpart_s[t] : 0.f;
    float d_t = (t < 64) ? g_sqpart_t[t] : 0.f;
    abs_s = block_sum_256(abs_s, red);
    sq_s  = block_sum_256(sq_s,  red);
    abs_t = block_sum_256(abs_t, red);
    sq_t  = block_sum_256(sq_t,  red);
    d_s   = block_sum_256(d_s,   red);
    d_t   = block_sum_256(d_t,   red);
    float loss = 0.2f * sqrtf(d_s) + abs_s + 0.001f * sqrtf(sq_s)
               + 0.2f * sqrtf(d_t) + abs_t + 0.001f * sqrtf(sq_t);
    for (int idx = NN * DD + t; idx < out_size; idx += 256)
        out[idx] = loss;
}

// ---------------- launch ----------------
extern "C" void kernel_launch(void* const* d_in, const int* in_sizes, int n_in,
                              void* d_out, int out_size) {
    const float* cur           = (const float*)d_in[0];
    const float* pre           = (const float*)d_in[1];
    const float* r_proj_s      = (const float*)d_in[2];
    const float* inc_s         = (const float*)d_in[3];
    const float* r_proj_t      = (const float*)d_in[4];
    const float* inc_t         = (const float*)d_in[5];
    const float* node_proj     = (const float*)d_in[6];
    const float* spa_edge_proj = (const float*)d_in[7];
    const float* tmp_edge_proj = (const float*)d_in[8];
    const float* theta_w       = (const float*)d_in[9];
    const float* theta_b       = (const float*)d_in[10];
    float* out = (float*)d_out;

    float *p_spa_emb, *p_tmp_emb, *p_node_fea, *p_spa_fea, *p_tmp_fea, *p_val;
    float *p_master_s, *p_master_t;
    float *p_deg_s, *p_deg_t, *p_rowabs_s, *p_rowsq_s, *p_rowabs_t, *p_rowsq_t;
    float *p_sqpart_s, *p_sqpart_t;
    __nv_bfloat16 *p_bhi_s, *p_blo_s, *p_bhi_t, *p_blo_t;
    __nv_bfloat16 *p_am_s, *p_rh_s, *p_rl_s, *p_am_t, *p_rh_t, *p_rl_t, *p_whi, *p_wlo;
    cudaGetSymbolAddress((void**)&p_spa_emb,  g_spa_emb);
    cudaGetSymbolAddress((void**)&p_tmp_emb,  g_tmp_emb);
    cudaGetSymbolAddress((void**)&p_node_fea, g_node_fea);
    cudaGetSymbolAddress((void**)&p_spa_fea,  g_spa_fea);
    cudaGetSymbolAddress((void**)&p_tmp_fea,  g_tmp_fea);
    cudaGetSymbolAddress((void**)&p_val,      g_val);
    cudaGetSymbolAddress((void**)&p_master_s, g_master_s);
    cudaGetSymbolAddress((void**)&p_master_t, g_master_t);
    cudaGetSymbolAddress((void**)&p_deg_s,    g_deg_s);
    cudaGetSymbolAddress((void**)&p_deg_t,    g_deg_t);
    cudaGetSymbolAddress((void**)&p_rowabs_s, g_rowabs_s);
    cudaGetSymbolAddress((void**)&p_rowsq_s,  g_rowsq_s);
    cudaGetSymbolAddress((void**)&p_rowabs_t, g_rowabs_t);
    cudaGetSymbolAddress((void**)&p_rowsq_t,  g_rowsq_t);
    cudaGetSymbolAddress((void**)&p_sqpart_s, g_sqpart_s);
    cudaGetSymbolAddress((void**)&p_sqpart_t, g_sqpart_t);
    cudaGetSymbolAddress((void**)&p_bhi_s,    g_bhi_s);
    cudaGetSymbolAddress((void**)&p_blo_s,    g_blo_s);
    cudaGetSymbolAddress((void**)&p_bhi_t,    g_bhi_t);
    cudaGetSymbolAddress((void**)&p_blo_t,    g_blo_t);
    cudaGetSymbolAddress((void**)&p_am_s,     g_am_s);
    cudaGetSymbolAddress((void**)&p_rh_s,     g_rh_s);
    cudaGetSymbolAddress((void**)&p_rl_s,     g_rl_s);
    cudaGetSymbolAddress((void**)&p_am_t,     g_am_t);
    cudaGetSymbolAddress((void**)&p_rh_t,     g_rh_t);
    cudaGetSymbolAddress((void**)&p_rl_t,     g_rl_t);
    cudaGetSymbolAddress((void**)&p_whi,      g_whi);
    cudaGetSymbolAddress((void**)&p_wlo,      g_wlo);

    static bool attr_set = false;
    static cudaStream_t s2 = nullptr;
    static cudaEvent_t evF = nullptr, evJ = nullptr;
    if (!attr_set) {
        cudaFuncSetAttribute(big_inc_mma_kernel,
                             cudaFuncAttributeMaxDynamicSharedMemorySize, BIG_SMEM);
        cudaFuncSetAttribute(projA_kernel,
                             cudaFuncAttributeMaxDynamicSharedMemorySize, FEA_SMEM);
        cudaFuncSetAttribute(projB_kernel,
                             cudaFuncAttributeMaxDynamicSharedMemorySize, FEA_SMEM);
        cudaFuncSetAttribute(final_kernel,
                             cudaFuncAttributeMaxDynamicSharedMemorySize, FEA_SMEM);
        cudaStreamCreateWithFlags(&s2, cudaStreamNonBlocking);
        cudaEventCreateWithFlags(&evF, cudaEventDisableTiming);
        cudaEventCreateWithFlags(&evJ, cudaEventDisableTiming);
        attr_set = true;
    }

    // ---- fork: presplit (DRAM-bound) on s2, concurrent with wbsplit/projA ----
    cudaEventRecord(evF, 0);
    cudaStreamWaitEvent(s2, evF, 0);
    presplit_kernel<<<dim3(NN, 2), 256, 0, s2>>>(inc_s, inc_t,
                                                 p_am_s, p_rh_s, p_rl_s,
                                                 p_am_t, p_rh_t, p_rl_t,
                                                 p_rowabs_s, p_rowsq_s, p_deg_s,
                                                 p_rowabs_t, p_rowsq_t, p_deg_t);
    cudaEventRecord(evJ, s2);

    // main stream (concurrent with presplit):
    wbsplit_kernel<<<608, 256>>>(cur, pre, r_proj_s, r_proj_t, node_proj,
                                 spa_edge_proj, tmp_edge_proj, theta_w,
                                 p_whi, p_wlo,
                                 p_bhi_s, p_blo_s, p_bhi_t, p_blo_t);
    projA_kernel<<<dim3(NN / 64, 3), 256, FEA_SMEM>>>(cur, p_whi, p_wlo,
                                                      p_master_s, p_master_t, p_node_fea);

    // join: big kernel needs presplit's outputs
    cudaStreamWaitEvent(0, evJ, 0);

    // BIG tensor-core fused incidence GEMMs (launch #4 -> ncu capture slot)
    big_inc_mma_kernel<<<dim3(2, 32, 2), 512, BIG_SMEM>>>(
        p_am_s, p_rh_s, p_rl_s, p_am_t, p_rh_t, p_rl_t,
        p_bhi_s, p_blo_s, p_bhi_t, p_blo_t, cur,
        p_master_s, p_master_t, p_deg_s, p_deg_t,
        p_spa_emb, p_tmp_emb, p_sqpart_s, p_sqpart_t);

    // spa/tmp feature projections (mma, one launch)
    projB_kernel<<<dim3(NN / 64, 2), 256, FEA_SMEM>>>(p_spa_emb, p_tmp_emb,
                                                      p_whi, p_wlo, p_spa_fea, p_tmp_fea);

    // attention + val
    attn_val_kernel<<<NN, 256>>>();

    // node_emb = relu(val @ theta_w^T + theta_b)  -> d_out[0 .. N*D)
    final_kernel<<<dim3(NN / 64), 256, FEA_SMEM>>>(p_val, p_whi, p_wlo, theta_b, out);

    // loss scalar -> d_out[N*D ...]
    finalize_kernel<<<1, 256>>>(out, out_size);
}